// round 13
// baseline (speedup 1.0000x reference)
#include <cuda_runtime.h>
#include <cstdint>

// Problem constants
#define B        64
#define N_SV     63
#define HID      512
#define NEW_W    28
#define NEW_H    28
#define NCELL    (NEW_W * NEW_H)     // 784
#define HT       8                   // h-channels per block (validated optimum)
#define NTHREADS 256
#define TILE_F   (HT * NCELL)        // 6272 floats per block tile
#define TILE_F8  (TILE_F / 8)        // 784 x 32B chunks per tile
#define NPAIR    (N_SV * HT)         // 504 (agent, channel) pairs per block

// 256-bit zero store with L2 evict_last (sm_103a requires the .v8.b32 form).
// The 102.8 MB output fits in the 126 MB L2; keeping its lines resident-dirty
// across graph replays avoids most DRAM writeback.
__device__ __forceinline__ void st_zero256_evict_last(void* p) {
    asm volatile(
        "st.global.L2::evict_last.v8.b32 [%0], {%1,%1,%1,%1,%1,%1,%1,%1};"
        :: "l"(p), "r"(0) : "memory");
}

// No-return global reduction max (guaranteed REDG.MAX, no ATOMG round-trip).
__device__ __forceinline__ void red_max_s32(int* p, int v) {
    asm volatile("red.global.max.s32 [%0], %1;" :: "l"(p), "r"(v) : "memory");
}

// ---------------------------------------------------------------------------
// Single fused kernel (converged structure).
// Each block exclusively owns output tile (b, h0..h0+8, all 784 cells).
//   Prologue: agent cells (63 threads) + this thread's <=2 enc values are
//             loaded FIRST, so their DRAM latency overlaps the fill and the
//             post-barrier patch runs from registers.
//   Phase A : 256-bit zero stores straight to global (evict_last); the
//             small remainder store issues first, the 3 full strides go
//             back-to-back for maximal store MLP.
//   barrier : orders zeros before patches within the block (zeros and
//             patches may target the same addresses).
//   Phase B : <=2 REDG.MAX per thread patch the occupied cells. Values
//             <= 0 skipped (they lose to the 0 init); survivors >= 0 so
//             int-compare on float bits is exact.
// ---------------------------------------------------------------------------
__global__ __launch_bounds__(NTHREADS)
void fused_raster_kernel(const float* __restrict__ pos,     // (B, N_SV, 3)
                         const float* __restrict__ enc,     // (B, N_SV, HID)
                         const int*   __restrict__ lengths, // (B,)
                         float* __restrict__ out)           // (B, HID, 28, 28)
{
    const int b   = blockIdx.x;
    const int h0  = blockIdx.y * HT;
    const int tid = threadIdx.x;

    __shared__ int sCell[N_SV];   // cell index per agent, -1 if invalid

    // --- Prologue 1: agent validity + cell index (first 63 threads) ---
    if (tid < N_SV) {
        int cell = -1;
        if (tid < lengths[b]) {
            const float x = pos[(b * N_SV + tid) * 3 + 0];
            const float y = pos[(b * N_SV + tid) * 3 + 1];
            // Reference math: int(x * 28 / 224), trunc toward zero
            int xI = (int)((x * (float)NEW_W) / 224.0f);
            int yI = (int)((y * (float)NEW_H) / 224.0f);
            if (xI < NEW_W && yI < NEW_H) {
                if (xI < 0) xI = 0;
                if (yI < 0) yI = 0;
                cell = xI * NEW_H + yI;
            }
        }
        sCell[tid] = cell;
    }

    // --- Prologue 2: hoist this thread's <=2 enc loads (streaming reads so
    //     they don't displace the pinned output lines in L2) ---
    const float* encB = enc + (size_t)b * N_SV * HID + h0;
    const int i0 = tid, i1 = tid + NTHREADS;
    const bool p0 = (i0 < NPAIR), p1 = (i1 < NPAIR);
    float v0 = 0.f, v1 = 0.f;
    if (p0) v0 = __ldcs(encB + (i0 >> 3) * HID + (i0 & (HT - 1)));
    if (p1) v1 = __ldcs(encB + (i1 >> 3) * HID + (i1 & (HT - 1)));

    // --- Phase A: zero the tile directly in global (256-bit, evict_last) ---
    // Tile base is 32B-aligned: (b*HID+h0)*NCELL*4 is a multiple of 3136.
    float* outB = out + ((size_t)b * HID + h0) * NCELL;
    char* outC = (char*)outB;
    // Remainder (16 threads) first, then 3 full strides back-to-back.
    if (tid < TILE_F8 - (TILE_F8 / NTHREADS) * NTHREADS)
        st_zero256_evict_last(outC + (size_t)(tid + (TILE_F8 / NTHREADS) * NTHREADS) * 32);
    #pragma unroll
    for (int k = 0; k < TILE_F8 / NTHREADS; k++)               // 3 iterations
        st_zero256_evict_last(outC + (size_t)(tid + k * NTHREADS) * 32);

    // Order: sCell writes visible + zeros complete before patches.
    __syncthreads();

    // --- Phase B: patch occupied cells with no-return REDG.MAX ---
    int* outBi = (int*)outB;
    if (p0 && v0 > 0.f) {
        const int c = sCell[i0 >> 3];
        if (c >= 0) red_max_s32(outBi + (i0 & (HT - 1)) * NCELL + c, __float_as_int(v0));
    }
    if (p1 && v1 > 0.f) {
        const int c = sCell[i1 >> 3];
        if (c >= 0) red_max_s32(outBi + (i1 & (HT - 1)) * NCELL + c, __float_as_int(v1));
    }
}

extern "C" void kernel_launch(void* const* d_in, const int* in_sizes, int n_in,
                              void* d_out, int out_size) {
    const float* pos     = (const float*)d_in[0];   // (B, N_SV, 3)
    const float* enc     = (const float*)d_in[1];   // (B, N_SV, HID)
    const int*   lengths = (const int*)d_in[2];     // (B,)

    dim3 grid(B, HID / HT);            // (64, 64) = 4096 blocks
    fused_raster_kernel<<<grid, NTHREADS>>>(pos, enc, lengths, (float*)d_out);
}

// round 14
// speedup vs baseline: 1.0111x; 1.0111x over previous
#include <cuda_runtime.h>
#include <cstdint>

// Problem constants
#define B        64
#define N_SV     63
#define HID      512
#define NEW_W    28
#define NEW_H    28
#define NCELL    (NEW_W * NEW_H)     // 784
#define HT       8                   // h-channels per block (validated optimum)
#define NTHREADS 256
#define TILE_F   (HT * NCELL)        // 6272 floats per block tile
#define TILE_F8  (TILE_F / 8)        // 784 x 32B chunks per tile
#define NPAIR    (N_SV * HT)         // 504 (agent, channel) pairs per block

// 256-bit zero store with L2 evict_last (sm_103a requires the .v8.b32 form).
// The 102.8 MB output fits in the 126 MB L2; keeping its lines resident-dirty
// across graph replays avoids most DRAM writeback (R7-validated).
__device__ __forceinline__ void st_zero256_evict_last(void* p) {
    asm volatile(
        "st.global.L2::evict_last.v8.b32 [%0], {%1,%1,%1,%1,%1,%1,%1,%1};"
        :: "l"(p), "r"(0) : "memory");
}

// No-return global reduction max (guaranteed REDG.MAX, no ATOMG round-trip).
__device__ __forceinline__ void red_max_s32(int* p, int v) {
    asm volatile("red.global.max.s32 [%0], %1;" :: "l"(p), "r"(v) : "memory");
}

// ---------------------------------------------------------------------------
// Single fused kernel — converged configuration (best measured: 19.07 us).
// Each block exclusively owns output tile (b, h0..h0+8, all 784 cells).
//   Prologue: agent cells (63 threads) + this thread's <=2 enc values are
//             loaded FIRST, so their DRAM latency overlaps the fill and the
//             post-barrier patch runs from registers.
//   Phase A : 3 full strides of 256-bit zero stores (evict_last) plus a
//             16-thread remainder — straight to global, no smem round-trip.
//   barrier : orders zeros before patches within the block (they may alias).
//   Phase B : <=2 REDG.MAX per thread patch the occupied cells. Values
//             <= 0 skipped (they lose to the 0 init); survivors >= 0 so
//             int-compare on float bits is exact.
// ---------------------------------------------------------------------------
__global__ __launch_bounds__(NTHREADS)
void fused_raster_kernel(const float* __restrict__ pos,     // (B, N_SV, 3)
                         const float* __restrict__ enc,     // (B, N_SV, HID)
                         const int*   __restrict__ lengths, // (B,)
                         float* __restrict__ out)           // (B, HID, 28, 28)
{
    const int b   = blockIdx.x;
    const int h0  = blockIdx.y * HT;
    const int tid = threadIdx.x;

    __shared__ int sCell[N_SV];   // cell index per agent, -1 if invalid

    // --- Prologue 1: agent validity + cell index (first 63 threads) ---
    if (tid < N_SV) {
        int cell = -1;
        if (tid < lengths[b]) {
            const float x = pos[(b * N_SV + tid) * 3 + 0];
            const float y = pos[(b * N_SV + tid) * 3 + 1];
            // Reference math: int(x * 28 / 224), trunc toward zero
            int xI = (int)((x * (float)NEW_W) / 224.0f);
            int yI = (int)((y * (float)NEW_H) / 224.0f);
            if (xI < NEW_W && yI < NEW_H) {
                if (xI < 0) xI = 0;
                if (yI < 0) yI = 0;
                cell = xI * NEW_H + yI;
            }
        }
        sCell[tid] = cell;
    }

    // --- Prologue 2: hoist this thread's <=2 enc loads (streaming reads so
    //     they don't displace the pinned output lines in L2) ---
    const float* encB = enc + (size_t)b * N_SV * HID + h0;
    const int i0 = tid, i1 = tid + NTHREADS;
    const bool p0 = (i0 < NPAIR), p1 = (i1 < NPAIR);
    float v0 = 0.f, v1 = 0.f;
    if (p0) v0 = __ldcs(encB + (i0 >> 3) * HID + (i0 & (HT - 1)));
    if (p1) v1 = __ldcs(encB + (i1 >> 3) * HID + (i1 & (HT - 1)));

    // --- Phase A: zero the tile directly in global (256-bit, evict_last) ---
    // Tile base is 32B-aligned: (b*HID+h0)*NCELL*4 is a multiple of 3136.
    float* outB = out + ((size_t)b * HID + h0) * NCELL;
    char* outC = (char*)outB;
    // 784 chunks / 256 threads = 3 full strides + 16-thread remainder.
    #pragma unroll
    for (int k = 0; k < TILE_F8 / NTHREADS; k++)               // 3 iterations
        st_zero256_evict_last(outC + (size_t)(tid + k * NTHREADS) * 32);
    if (tid < TILE_F8 - (TILE_F8 / NTHREADS) * NTHREADS)       // last 16
        st_zero256_evict_last(outC + (size_t)(tid + (TILE_F8 / NTHREADS) * NTHREADS) * 32);

    // Order: sCell writes visible + zeros complete before patches.
    __syncthreads();

    // --- Phase B: patch occupied cells with no-return REDG.MAX ---
    int* outBi = (int*)outB;
    if (p0 && v0 > 0.f) {
        const int c = sCell[i0 >> 3];
        if (c >= 0) red_max_s32(outBi + (i0 & (HT - 1)) * NCELL + c, __float_as_int(v0));
    }
    if (p1 && v1 > 0.f) {
        const int c = sCell[i1 >> 3];
        if (c >= 0) red_max_s32(outBi + (i1 & (HT - 1)) * NCELL + c, __float_as_int(v1));
    }
}

extern "C" void kernel_launch(void* const* d_in, const int* in_sizes, int n_in,
                              void* d_out, int out_size) {
    const float* pos     = (const float*)d_in[0];   // (B, N_SV, 3)
    const float* enc     = (const float*)d_in[1];   // (B, N_SV, HID)
    const int*   lengths = (const int*)d_in[2];     // (B,)

    dim3 grid(B, HID / HT);            // (64, 64) = 4096 blocks
    fused_raster_kernel<<<grid, NTHREADS>>>(pos, enc, lengths, (float*)d_out);
}

// round 15
// speedup vs baseline: 1.0312x; 1.0199x over previous
#include <cuda_runtime.h>
#include <cstdint>

// Problem constants
#define B        64
#define N_SV     63
#define HID      512
#define NEW_W    28
#define NEW_H    28
#define NCELL    (NEW_W * NEW_H)     // 784
#define HT       8                   // h-channels per block (validated optimum)
#define NTHREADS 256
#define TILE_F   (HT * NCELL)        // 6272 floats per block tile
#define TILE_F8  (TILE_F / 8)        // 784 x 32B chunks per tile
#define NPAIR    (N_SV * HT)         // 504 (agent, channel) pairs per block

// 256-bit zero store with L2 evict_last (sm_103a requires the .v8.b32 form).
// The 102.8 MB output fits in the 126 MB L2; keeping its lines resident-dirty
// across graph replays avoids most DRAM writeback (R7-validated).
__device__ __forceinline__ void st_zero256_evict_last(void* p) {
    asm volatile(
        "st.global.L2::evict_last.v8.b32 [%0], {%1,%1,%1,%1,%1,%1,%1,%1};"
        :: "l"(p), "r"(0) : "memory");
}

// No-return global reduction max (guaranteed REDG.MAX, no ATOMG round-trip).
__device__ __forceinline__ void red_max_s32(int* p, int v) {
    asm volatile("red.global.max.s32 [%0], %1;" :: "l"(p), "r"(v) : "memory");
}

// Per-thread agent->cell computation. pos rows and lengths[b] are L1-resident
// broadcast loads (63x3 floats per block); redundant recompute across the 8
// threads sharing an agent is far cheaper than 4 MB of wasted enc traffic.
__device__ __forceinline__ int agent_cell(const float* __restrict__ pos,
                                          int b, int a, int len) {
    if (a >= len) return -1;
    const float x = pos[(b * N_SV + a) * 3 + 0];
    const float y = pos[(b * N_SV + a) * 3 + 1];
    // Reference math: int(x * 28 / 224), trunc toward zero
    int xI = (int)((x * (float)NEW_W) / 224.0f);
    int yI = (int)((y * (float)NEW_H) / 224.0f);
    if (xI >= NEW_W || yI >= NEW_H) return -1;
    if (xI < 0) xI = 0;
    if (yI < 0) yI = 0;
    return xI * NEW_H + yI;
}

// ---------------------------------------------------------------------------
// Single fused kernel. LTS-traffic-minimized:
//   - enc is loaded ONLY for valid agents (~halves the 8.2 MB read stream;
//     the kernel sits at the ~6.3 TB/s LTS chip cap, so bytes == time).
//   - zero stores are 256-bit evict_last straight to global.
//   - patches are no-return REDG.MAX (values <= 0 skipped: they lose to the
//     0 init; survivors >= 0 so int-compare on float bits is exact).
// Each block exclusively owns output tile (b, h0..h0+8, all 784 cells).
// The barrier orders zeros before patches (they may alias).
// ---------------------------------------------------------------------------
__global__ __launch_bounds__(NTHREADS)
void fused_raster_kernel(const float* __restrict__ pos,     // (B, N_SV, 3)
                         const float* __restrict__ enc,     // (B, N_SV, HID)
                         const int*   __restrict__ lengths, // (B,)
                         float* __restrict__ out)           // (B, HID, 28, 28)
{
    const int b   = blockIdx.x;
    const int h0  = blockIdx.y * HT;
    const int tid = threadIdx.x;

    // --- Prologue: per-thread validity, then gated enc loads (hoisted so
    //     their DRAM latency overlaps the fill phase) ---
    const int len = lengths[b];                 // broadcast, L1-resident
    const float* encB = enc + (size_t)b * N_SV * HID + h0;

    const int i0 = tid, i1 = tid + NTHREADS;
    const int c0 = (i0 < NPAIR) ? agent_cell(pos, b, i0 >> 3, len) : -1;
    const int c1 = (i1 < NPAIR) ? agent_cell(pos, b, i1 >> 3, len) : -1;
    float v0 = 0.f, v1 = 0.f;
    if (c0 >= 0) v0 = __ldcs(encB + (i0 >> 3) * HID + (i0 & (HT - 1)));
    if (c1 >= 0) v1 = __ldcs(encB + (i1 >> 3) * HID + (i1 & (HT - 1)));

    // --- Phase A: zero the tile directly in global (256-bit, evict_last) ---
    // Tile base is 32B-aligned: (b*HID+h0)*NCELL*4 is a multiple of 3136.
    float* outB = out + ((size_t)b * HID + h0) * NCELL;
    char* outC = (char*)outB;
    // 784 chunks / 256 threads = 3 full strides + 16-thread remainder.
    #pragma unroll
    for (int k = 0; k < TILE_F8 / NTHREADS; k++)               // 3 iterations
        st_zero256_evict_last(outC + (size_t)(tid + k * NTHREADS) * 32);
    if (tid < TILE_F8 - (TILE_F8 / NTHREADS) * NTHREADS)       // last 16
        st_zero256_evict_last(outC + (size_t)(tid + (TILE_F8 / NTHREADS) * NTHREADS) * 32);

    // Order: zeros complete before patches (same addresses may be touched).
    __syncthreads();

    // --- Phase B: patch occupied cells with no-return REDG.MAX ---
    int* outBi = (int*)outB;
    if (c0 >= 0 && v0 > 0.f)
        red_max_s32(outBi + (i0 & (HT - 1)) * NCELL + c0, __float_as_int(v0));
    if (c1 >= 0 && v1 > 0.f)
        red_max_s32(outBi + (i1 & (HT - 1)) * NCELL + c1, __float_as_int(v1));
}

extern "C" void kernel_launch(void* const* d_in, const int* in_sizes, int n_in,
                              void* d_out, int out_size) {
    const float* pos     = (const float*)d_in[0];   // (B, N_SV, 3)
    const float* enc     = (const float*)d_in[1];   // (B, N_SV, HID)
    const int*   lengths = (const int*)d_in[2];     // (B,)

    dim3 grid(B, HID / HT);            // (64, 64) = 4096 blocks
    fused_raster_kernel<<<grid, NTHREADS>>>(pos, enc, lengths, (float*)d_out);
}